// round 8
// baseline (speedup 1.0000x reference)
#include <cuda_runtime.h>
#include <cuda_bf16.h>
#include <cuda_fp16.h>
#include <cstdint>

#define NN 50000
#define EE 640000
#define DD 128          // feature dim
#define KK 256          // 2*DD
#define DOUT 128
#define CAP 80          // max neighbors per node (Poisson(12.8): P(>=80) ~ 1e-45)

// ---------------- scratch (static device globals; no allocation) -------------
__device__ float  g_Y[(size_t)NN * DD];     // x @ W1^T   fp32 (25.6 MB)
__device__ __half g_Z[(size_t)NN * DD];     // x @ W2^T   fp16 (12.8 MB)
__device__ int    g_bucket[(size_t)NN * CAP];  // adjacency buckets (16 MB)
__device__ int    g_cnt[NN];
// pre-split bf16 operands
__device__ __nv_bfloat16 g_xhi[(size_t)NN * DD];
__device__ __nv_bfloat16 g_xlo[(size_t)NN * DD];
__device__ __nv_bfloat16 g_whi[DOUT * KK];
__device__ __nv_bfloat16 g_wlo[DOUT * KK];

// ---------------- 0) zero counters -------------------------------------------
__global__ void zero_kernel() {
    int i = blockIdx.x * blockDim.x + threadIdx.x;
    if (i < NN) g_cnt[i] = 0;
}

// ---------------- 1) decode edge index + bucket insert (fused) ----------------
// int64 little-endian with values < 50000 => odd 32-bit words all zero.
__global__ void decode_bucket_kernel(const void* __restrict__ ei) {
    const int* ei32 = (const int*)ei;
    int t = threadIdx.x;
    int accw = ei32[2 * t + 1] | ei32[2 * (t + 256) + 1];
    int is32 = __syncthreads_or(accw);      // nonzero -> int32 indices

    int e = blockIdx.x * blockDim.x + t;
    if (e >= EE) return;
    int r, c;
    if (!is32) {
        const long long* p = (const long long*)ei;
        r = (int)p[e];
        c = (int)p[(size_t)EE + e];
    } else {
        r = ei32[e];
        c = ei32[EE + e];
    }
    r = min(max(r, 0), NN - 1);
    c = min(max(c, 0), NN - 1);
    int slot = atomicAdd(&g_cnt[r], 1);
    if (slot < CAP)
        g_bucket[(size_t)r * CAP + slot] = c;
}

// ---------------- 2) one-pass bf16 hi/lo split of x and W ---------------------
#define NX4 ((NN * DD) / 4)          // 1,600,000 float4 chunks of x
#define NW4 ((DOUT * KK) / 4)        // 8,192 float4 chunks of W
__global__ void split_kernel(const float* __restrict__ x, const float* __restrict__ W) {
    int i = blockIdx.x * blockDim.x + threadIdx.x;
    if (i < NX4) {
        float4 v = ((const float4*)x)[i];
        __nv_bfloat16 h0 = __float2bfloat16(v.x), h1 = __float2bfloat16(v.y);
        __nv_bfloat16 h2 = __float2bfloat16(v.z), h3 = __float2bfloat16(v.w);
        __nv_bfloat162* hp = (__nv_bfloat162*)(g_xhi + (size_t)i * 4);
        hp[0] = __nv_bfloat162(h0, h1);
        hp[1] = __nv_bfloat162(h2, h3);
        __nv_bfloat162* lp = (__nv_bfloat162*)(g_xlo + (size_t)i * 4);
        lp[0] = __nv_bfloat162(__float2bfloat16(v.x - __bfloat162float(h0)),
                               __float2bfloat16(v.y - __bfloat162float(h1)));
        lp[1] = __nv_bfloat162(__float2bfloat16(v.z - __bfloat162float(h2)),
                               __float2bfloat16(v.w - __bfloat162float(h3)));
    } else if (i < NX4 + NW4) {
        int j = i - NX4;
        float4 v = ((const float4*)W)[j];
        __nv_bfloat16 h0 = __float2bfloat16(v.x), h1 = __float2bfloat16(v.y);
        __nv_bfloat16 h2 = __float2bfloat16(v.z), h3 = __float2bfloat16(v.w);
        __nv_bfloat162* hp = (__nv_bfloat162*)(g_whi + (size_t)j * 4);
        hp[0] = __nv_bfloat162(h0, h1);
        hp[1] = __nv_bfloat162(h2, h3);
        __nv_bfloat162* lp = (__nv_bfloat162*)(g_wlo + (size_t)j * 4);
        lp[0] = __nv_bfloat162(__float2bfloat16(v.x - __bfloat162float(h0)),
                               __float2bfloat16(v.y - __bfloat162float(h1)));
        lp[1] = __nv_bfloat162(__float2bfloat16(v.z - __bfloat162float(h2)),
                               __float2bfloat16(v.w - __bfloat162float(h3)));
    }
}

// ---------------- 3) tensor-core GEMM: [Y|Z] = x @ [W1;W2]^T ------------------
// fp32 emulated via bf16 split: a*b ~= ah*bh + ah*bl + al*bh (operands pre-split)
#define GM 128
#define GN 128
#define GK 32
#define APAD 8          // row stride 40 halves = 80B (16B aligned, conflict-free)

__device__ __forceinline__ void mma_bf16(float c[4], const uint32_t a[4],
                                         uint32_t b0, uint32_t b1) {
    asm volatile(
        "mma.sync.aligned.m16n8k16.row.col.f32.bf16.bf16.f32 "
        "{%0,%1,%2,%3}, {%4,%5,%6,%7}, {%8,%9}, {%0,%1,%2,%3};"
        : "+f"(c[0]), "+f"(c[1]), "+f"(c[2]), "+f"(c[3])
        : "r"(a[0]), "r"(a[1]), "r"(a[2]), "r"(a[3]), "r"(b0), "r"(b1));
}

__global__ __launch_bounds__(256, 2)
void gemm_kernel() {
    __shared__ __nv_bfloat16 As_hi[GM][GK + APAD];
    __shared__ __nv_bfloat16 As_lo[GM][GK + APAD];
    __shared__ __nv_bfloat16 Bs_hi[GN][GK + APAD];
    __shared__ __nv_bfloat16 Bs_lo[GN][GK + APAD];

    int t = threadIdx.x;
    int block_m = blockIdx.x * GM;
    int half = blockIdx.y;
    int wid = t >> 5, lane = t & 31;
    int wm = (wid & 3) * 32;
    int wn = (wid >> 2) * 64;
    int g = lane >> 2, tig = lane & 3;

    float acc[2][8][4];
#pragma unroll
    for (int mi = 0; mi < 2; mi++)
#pragma unroll
        for (int ni = 0; ni < 8; ni++)
#pragma unroll
            for (int q = 0; q < 4; q++) acc[mi][ni][q] = 0.f;

    const __nv_bfloat16* wh = g_whi + (half ? DD : 0);
    const __nv_bfloat16* wl = g_wlo + (half ? DD : 0);

    // tile copy helpers: 512 uint4 chunks per 128x32 bf16 tile; 2 per thread
    for (int k0 = 0; k0 < DD; k0 += GK) {
#pragma unroll
        for (int i = 0; i < 2; i++) {
            int lin = t + i * 256;           // uint4 chunk index (8 bf16)
            int row = lin >> 2;              // 4 chunks per row
            int kq = (lin & 3) * 8;
            int grow = block_m + row;
            uint4 zh = make_uint4(0, 0, 0, 0), zl = make_uint4(0, 0, 0, 0);
            if (grow < NN) {
                zh = *(const uint4*)(g_xhi + (size_t)grow * DD + k0 + kq);
                zl = *(const uint4*)(g_xlo + (size_t)grow * DD + k0 + kq);
            }
            *(uint4*)&As_hi[row][kq] = zh;
            *(uint4*)&As_lo[row][kq] = zl;
            // B tile: rows are output features j (0..127)
            *(uint4*)&Bs_hi[row][kq] = *(const uint4*)(wh + (size_t)row * KK + k0 + kq);
            *(uint4*)&Bs_lo[row][kq] = *(const uint4*)(wl + (size_t)row * KK + k0 + kq);
        }
        __syncthreads();

#pragma unroll
        for (int kk = 0; kk < GK; kk += 16) {
            uint32_t ahi[2][4], alo[2][4];
#pragma unroll
            for (int mi = 0; mi < 2; mi++) {
                int r0 = wm + mi * 16 + g;
                int r1 = r0 + 8;
                int c0 = kk + 2 * tig;
                int c1 = c0 + 8;
                ahi[mi][0] = *(const uint32_t*)&As_hi[r0][c0];
                ahi[mi][1] = *(const uint32_t*)&As_hi[r1][c0];
                ahi[mi][2] = *(const uint32_t*)&As_hi[r0][c1];
                ahi[mi][3] = *(const uint32_t*)&As_hi[r1][c1];
                alo[mi][0] = *(const uint32_t*)&As_lo[r0][c0];
                alo[mi][1] = *(const uint32_t*)&As_lo[r1][c0];
                alo[mi][2] = *(const uint32_t*)&As_lo[r0][c1];
                alo[mi][3] = *(const uint32_t*)&As_lo[r1][c1];
            }
#pragma unroll
            for (int ni = 0; ni < 8; ni++) {
                int n = wn + ni * 8 + g;
                int c0 = kk + 2 * tig;
                int c1 = c0 + 8;
                uint32_t bh0 = *(const uint32_t*)&Bs_hi[n][c0];
                uint32_t bh1 = *(const uint32_t*)&Bs_hi[n][c1];
                uint32_t bl0 = *(const uint32_t*)&Bs_lo[n][c0];
                uint32_t bl1 = *(const uint32_t*)&Bs_lo[n][c1];
#pragma unroll
                for (int mi = 0; mi < 2; mi++) {
                    mma_bf16(acc[mi][ni], ahi[mi], bh0, bh1);
                    mma_bf16(acc[mi][ni], ahi[mi], bl0, bl1);
                    mma_bf16(acc[mi][ni], alo[mi], bh0, bh1);
                }
            }
        }
        __syncthreads();
    }

    if (half) {
#pragma unroll
        for (int mi = 0; mi < 2; mi++) {
#pragma unroll
            for (int ni = 0; ni < 8; ni++) {
                int r0 = block_m + wm + mi * 16 + g;
                int r1 = r0 + 8;
                int n = wn + ni * 8 + 2 * tig;
                if (r0 < NN)
                    *(__half2*)(g_Z + (size_t)r0 * DD + n) =
                        __floats2half2_rn(acc[mi][ni][0], acc[mi][ni][1]);
                if (r1 < NN)
                    *(__half2*)(g_Z + (size_t)r1 * DD + n) =
                        __floats2half2_rn(acc[mi][ni][2], acc[mi][ni][3]);
            }
        }
    } else {
#pragma unroll
        for (int mi = 0; mi < 2; mi++) {
#pragma unroll
            for (int ni = 0; ni < 8; ni++) {
                int r0 = block_m + wm + mi * 16 + g;
                int r1 = r0 + 8;
                int n = wn + ni * 8 + 2 * tig;
                if (r0 < NN)
                    *(float2*)(g_Y + (size_t)r0 * DD + n) =
                        make_float2(acc[mi][ni][0], acc[mi][ni][1]);
                if (r1 < NN)
                    *(float2*)(g_Y + (size_t)r1 * DD + n) =
                        make_float2(acc[mi][ni][2], acc[mi][ni][3]);
            }
        }
    }
}

// ---------------- 4) fused gather + epilogue ----------------------------------
// out[node] = relu( Y[node] + b + (sum_{c in bucket} Z_fp16[c]) / (cnt + 1e-8) )
__global__ void final_kernel(const float* __restrict__ b, float* __restrict__ out) {
    int gtid = blockIdx.x * blockDim.x + threadIdx.x;
    int node = gtid >> 5;
    int lane = gtid & 31;
    if (node >= NN) return;
    int cnt = g_cnt[node];
    int m = min(cnt, CAP);
    const int* bucket = g_bucket + (size_t)node * CAP;
    float4 acc = make_float4(0.f, 0.f, 0.f, 0.f);
    int c = (m > 0) ? bucket[0] : 0;
    for (int j = 0; j < m; j++) {
        int cn = (j + 1 < m) ? bucket[j + 1] : 0;   // prefetch next col idx
        uint2 raw = *(const uint2*)(g_Z + (size_t)c * DD + lane * 4);
        float2 p0 = __half22float2(*(__half2*)&raw.x);
        float2 p1 = __half22float2(*(__half2*)&raw.y);
        acc.x += p0.x; acc.y += p0.y; acc.z += p1.x; acc.w += p1.y;
        c = cn;
    }
    float inv = 1.0f / ((float)cnt + 1e-8f);
    float4 y  = *(const float4*)(g_Y + (size_t)node * DD + lane * 4);
    float4 bb = *(const float4*)(b + lane * 4);
    float4 o;
    o.x = fmaxf(y.x + bb.x + acc.x * inv, 0.f);
    o.y = fmaxf(y.y + bb.y + acc.y * inv, 0.f);
    o.z = fmaxf(y.z + bb.z + acc.z * inv, 0.f);
    o.w = fmaxf(y.w + bb.w + acc.w * inv, 0.f);
    *(float4*)(out + (size_t)node * DOUT + lane * 4) = o;
}

// ---------------- launch ------------------------------------------------------
// Fork: bucket build (side stream) overlaps split+GEMM (main stream); join
// before the final gather. Handles are leaked intentionally (kernel_launch is
// invoked only for correctness + capture; replays re-execute the graph).
extern "C" void kernel_launch(void* const* d_in, const int* in_sizes, int n_in,
                              void* d_out, int out_size) {
    const float* x   = (const float*)d_in[0];
    const void*  ei  = d_in[1];
    const float* W   = (const float*)d_in[2];
    const float* b   = (const float*)d_in[3];
    float*       out = (float*)d_out;

    cudaStream_t s1;
    cudaEvent_t  e_fork, e_join;
    cudaStreamCreateWithFlags(&s1, cudaStreamNonBlocking);
    cudaEventCreateWithFlags(&e_fork, cudaEventDisableTiming);
    cudaEventCreateWithFlags(&e_join, cudaEventDisableTiming);

    cudaEventRecord(e_fork, 0);
    cudaStreamWaitEvent(s1, e_fork, 0);

    // adjacency branch (side stream)
    zero_kernel<<<(NN + 255) / 256, 256, 0, s1>>>();
    decode_bucket_kernel<<<(EE + 255) / 256, 256, 0, s1>>>(ei);
    cudaEventRecord(e_join, s1);

    // main stream: split then GEMM (overlaps bucket build)
    split_kernel<<<(NX4 + NW4 + 255) / 256, 256>>>(x, W);
    dim3 ggrid((NN + GM - 1) / GM, 2);
    gemm_kernel<<<ggrid, 256>>>();

    cudaStreamWaitEvent(0, e_join, 0);
    final_kernel<<<(NN * 32 + 255) / 256, 256>>>(b, out);
}

// round 11
// speedup vs baseline: 1.0461x; 1.0461x over previous
#include <cuda_runtime.h>
#include <cuda_bf16.h>
#include <cuda_fp16.h>
#include <cstdint>

#define NN 50000
#define EE 640000
#define DD 128          // feature dim (GEMM K)
#define KK 256          // W row length (2*DD)
#define DOUT 128
#define CAP 80          // max neighbors per node (Poisson(12.8): P(>=80) ~ 1e-45)

// ---------------- scratch (static device globals; no allocation) -------------
__device__ float  g_Y[(size_t)NN * DD];     // x @ W1^T   fp32 (25.6 MB)
__device__ __half g_Z[(size_t)NN * DD];     // x @ W2^T   fp16 (12.8 MB)
__device__ int    g_bucket[(size_t)NN * CAP];  // adjacency buckets (16 MB)
__device__ int    g_cnt[NN];
// pre-split bf16 operands
__device__ __nv_bfloat16 g_xhi[(size_t)NN * DD];
__device__ __nv_bfloat16 g_xlo[(size_t)NN * DD];
__device__ __nv_bfloat16 g_whi[DOUT * KK];
__device__ __nv_bfloat16 g_wlo[DOUT * KK];

// ---------------- 0) zero counters -------------------------------------------
__global__ void zero_kernel() {
    int i = blockIdx.x * blockDim.x + threadIdx.x;
    if (i < NN) g_cnt[i] = 0;
}

// ---------------- 1) decode edge index + bucket insert (fused) ----------------
__global__ void decode_bucket_kernel(const void* __restrict__ ei) {
    const int* ei32 = (const int*)ei;
    int t = threadIdx.x;
    int accw = ei32[2 * t + 1] | ei32[2 * (t + 256) + 1];
    int is32 = __syncthreads_or(accw);      // nonzero -> int32 indices

    int e = blockIdx.x * blockDim.x + t;
    if (e >= EE) return;
    int r, c;
    if (!is32) {
        const long long* p = (const long long*)ei;
        r = (int)p[e];
        c = (int)p[(size_t)EE + e];
    } else {
        r = ei32[e];
        c = ei32[EE + e];
    }
    r = min(max(r, 0), NN - 1);
    c = min(max(c, 0), NN - 1);
    int slot = atomicAdd(&g_cnt[r], 1);
    if (slot < CAP)
        g_bucket[(size_t)r * CAP + slot] = c;
}

// ---------------- 2) one-pass bf16 hi/lo split of x and W ---------------------
#define NX4 ((NN * DD) / 4)
#define NW4 ((DOUT * KK) / 4)
__global__ void split_kernel(const float* __restrict__ x, const float* __restrict__ W) {
    int i = blockIdx.x * blockDim.x + threadIdx.x;
    if (i < NX4) {
        float4 v = ((const float4*)x)[i];
        __nv_bfloat16 h0 = __float2bfloat16(v.x), h1 = __float2bfloat16(v.y);
        __nv_bfloat16 h2 = __float2bfloat16(v.z), h3 = __float2bfloat16(v.w);
        __nv_bfloat162* hp = (__nv_bfloat162*)(g_xhi + (size_t)i * 4);
        hp[0] = __nv_bfloat162(h0, h1);
        hp[1] = __nv_bfloat162(h2, h3);
        __nv_bfloat162* lp = (__nv_bfloat162*)(g_xlo + (size_t)i * 4);
        lp[0] = __nv_bfloat162(__float2bfloat16(v.x - __bfloat162float(h0)),
                               __float2bfloat16(v.y - __bfloat162float(h1)));
        lp[1] = __nv_bfloat162(__float2bfloat16(v.z - __bfloat162float(h2)),
                               __float2bfloat16(v.w - __bfloat162float(h3)));
    } else if (i < NX4 + NW4) {
        int j = i - NX4;
        float4 v = ((const float4*)W)[j];
        __nv_bfloat16 h0 = __float2bfloat16(v.x), h1 = __float2bfloat16(v.y);
        __nv_bfloat16 h2 = __float2bfloat16(v.z), h3 = __float2bfloat16(v.w);
        __nv_bfloat162* hp = (__nv_bfloat162*)(g_whi + (size_t)j * 4);
        hp[0] = __nv_bfloat162(h0, h1);
        hp[1] = __nv_bfloat162(h2, h3);
        __nv_bfloat162* lp = (__nv_bfloat162*)(g_wlo + (size_t)j * 4);
        lp[0] = __nv_bfloat162(__float2bfloat16(v.x - __bfloat162float(h0)),
                               __float2bfloat16(v.y - __bfloat162float(h1)));
        lp[1] = __nv_bfloat162(__float2bfloat16(v.z - __bfloat162float(h2)),
                               __float2bfloat16(v.w - __bfloat162float(h3)));
    }
}

// ---------------- 3) GEMM via mma.sync + ldmatrix + cp.async double buffer ---
// [Y|Z] = x @ [W1;W2]^T, 3-term bf16 split, CTA tile 128x128, K=128 in 4 chunks.
#define GM 128
#define GK 32
#define ROWP 40                 // smem row stride in halves (80B, LDSM conflict-free)
#define TILE_B (GM * ROWP * 2)  // 10240 bytes per 128x32 bf16 tile
#define SMEM_TOTAL (8 * TILE_B) // 2 stages x (Ahi,Alo,Bhi,Blo)

__device__ __forceinline__ uint32_t smem_u32(const void* p) {
    uint32_t a;
    asm("{ .reg .u64 t; cvta.to.shared.u64 t, %1; cvt.u32.u64 %0, t; }"
        : "=r"(a) : "l"(p));
    return a;
}

#define LDSM4(r, addr) \
    asm volatile("ldmatrix.sync.aligned.m8n8.x4.shared.b16 {%0,%1,%2,%3}, [%4];" \
                 : "=r"((r)[0]), "=r"((r)[1]), "=r"((r)[2]), "=r"((r)[3])       \
                 : "r"(addr))

__device__ __forceinline__ void mma_bf16(float c[4], const uint32_t a[4],
                                         uint32_t b0, uint32_t b1) {
    asm volatile(
        "mma.sync.aligned.m16n8k16.row.col.f32.bf16.bf16.f32 "
        "{%0,%1,%2,%3}, {%4,%5,%6,%7}, {%8,%9}, {%0,%1,%2,%3};"
        : "+f"(c[0]), "+f"(c[1]), "+f"(c[2]), "+f"(c[3])
        : "r"(a[0]), "r"(a[1]), "r"(a[2]), "r"(a[3]), "r"(b0), "r"(b1));
}

__device__ __forceinline__ void load_stage(uint32_t sbase, int s, int k0,
                                           int block_m, int halfoff, int t) {
#pragma unroll
    for (int j = 0; j < 8; j++) {
        int i = t + j * 256;           // 2048 cp.async chunks of 16B
        int tile = i >> 9;             // 0 Ahi, 1 Alo, 2 Bhi, 3 Blo
        int idx = i & 511;
        int row = idx >> 2;
        int kq = (idx & 3) * 8;
        const __nv_bfloat16* src;
        int srcsize = 16;
        if (tile < 2) {
            int grow = block_m + row;
            if (grow >= NN) { grow = NN - 1; srcsize = 0; }
            src = (tile == 0 ? g_xhi : g_xlo) + (size_t)grow * DD + k0 + kq;
        } else {
            src = (tile == 2 ? g_whi : g_wlo) + (size_t)row * KK + halfoff + k0 + kq;
        }
        uint32_t dst = sbase + (uint32_t)((tile * 2 + s) * TILE_B
                                          + (row * ROWP + kq) * 2);
        asm volatile("cp.async.cg.shared.global [%0], [%1], 16, %2;"
                     :: "r"(dst), "l"(src), "r"(srcsize));
    }
}

__global__ __launch_bounds__(256, 2)
void gemm_kernel() {
    extern __shared__ char smem[];
    uint32_t sbase = smem_u32(smem);

    int t = threadIdx.x;
    int wid = t >> 5, lane = t & 31;
    int block_m = blockIdx.x * GM;
    int halfsel = blockIdx.y;
    int halfoff = halfsel ? DD : 0;
    int wm = (wid & 3) * 32;            // warp rows
    int wn = (wid >> 2) * 64;           // warp cols
    int g = lane >> 2, tig = lane & 3;
    int frow = lane & 15;               // ldmatrix lane row
    int fcol = (lane >> 4) * 8;         // ldmatrix lane k-offset

    float acc[2][8][4];
#pragma unroll
    for (int mi = 0; mi < 2; mi++)
#pragma unroll
        for (int ni = 0; ni < 8; ni++)
#pragma unroll
            for (int q = 0; q < 4; q++) acc[mi][ni][q] = 0.f;

    load_stage(sbase, 0, 0, block_m, halfoff, t);
    asm volatile("cp.async.commit_group;");

#pragma unroll
    for (int kt = 0; kt < 4; kt++) {
        int s = kt & 1;
        if (kt < 3) {
            load_stage(sbase, s ^ 1, (kt + 1) * GK, block_m, halfoff, t);
            asm volatile("cp.async.commit_group;");
            asm volatile("cp.async.wait_group 1;");
        } else {
            asm volatile("cp.async.wait_group 0;");
        }
        __syncthreads();

        uint32_t aHi = sbase + (0 * 2 + s) * TILE_B;
        uint32_t aLo = sbase + (1 * 2 + s) * TILE_B;
        uint32_t bHi = sbase + (2 * 2 + s) * TILE_B;
        uint32_t bLo = sbase + (3 * 2 + s) * TILE_B;

#pragma unroll
        for (int kk16 = 0; kk16 < 2; kk16++) {
            int kk = kk16 * 16;
            uint32_t ah[2][4], al[2][4];
#pragma unroll
            for (int mi = 0; mi < 2; mi++) {
                uint32_t aoff = (uint32_t)(((wm + mi * 16 + frow) * ROWP
                                            + kk + fcol) * 2);
                LDSM4(ah[mi], aHi + aoff);
                LDSM4(al[mi], aLo + aoff);
            }
#pragma unroll
            for (int nj = 0; nj < 4; nj++) {
                uint32_t bh[4], bl[4];
                uint32_t boff = (uint32_t)(((wn + nj * 16 + frow) * ROWP
                                            + kk + fcol) * 2);
                LDSM4(bh, bHi + boff);
                LDSM4(bl, bLo + boff);
#pragma unroll
                for (int p = 0; p < 2; p++) {
                    int ni = nj * 2 + p;
#pragma unroll
                    for (int mi = 0; mi < 2; mi++) {
                        mma_bf16(acc[mi][ni], ah[mi], bh[p], bh[2 + p]);
                        mma_bf16(acc[mi][ni], ah[mi], bl[p], bl[2 + p]);
                        mma_bf16(acc[mi][ni], al[mi], bh[p], bh[2 + p]);
                    }
                }
            }
        }
        __syncthreads();
    }

    if (halfsel) {
#pragma unroll
        for (int mi = 0; mi < 2; mi++) {
#pragma unroll
            for (int ni = 0; ni < 8; ni++) {
                int r0 = block_m + wm + mi * 16 + g;
                int r1 = r0 + 8;
                int n = wn + ni * 8 + 2 * tig;
                if (r0 < NN)
                    *(__half2*)(g_Z + (size_t)r0 * DD + n) =
                        __floats2half2_rn(acc[mi][ni][0], acc[mi][ni][1]);
                if (r1 < NN)
                    *(__half2*)(g_Z + (size_t)r1 * DD + n) =
                        __floats2half2_rn(acc[mi][ni][2], acc[mi][ni][3]);
            }
        }
    } else {
#pragma unroll
        for (int mi = 0; mi < 2; mi++) {
#pragma unroll
            for (int ni = 0; ni < 8; ni++) {
                int r0 = block_m + wm + mi * 16 + g;
                int r1 = r0 + 8;
                int n = wn + ni * 8 + 2 * tig;
                if (r0 < NN)
                    *(float2*)(g_Y + (size_t)r0 * DD + n) =
                        make_float2(acc[mi][ni][0], acc[mi][ni][1]);
                if (r1 < NN)
                    *(float2*)(g_Y + (size_t)r1 * DD + n) =
                        make_float2(acc[mi][ni][2], acc[mi][ni][3]);
            }
        }
    }
}

// ---------------- 4) fused gather + epilogue ----------------------------------
// out[node] = relu( Y[node] + b + (sum_{c in bucket} Z_fp16[c]) / (cnt + 1e-8) )
__global__ void final_kernel(const float* __restrict__ b, float* __restrict__ out) {
    int gtid = blockIdx.x * blockDim.x + threadIdx.x;
    int node = gtid >> 5;
    int lane = gtid & 31;
    if (node >= NN) return;
    int cnt = g_cnt[node];
    int m = min(cnt, CAP);
    const int* bucket = g_bucket + (size_t)node * CAP;
    float4 acc = make_float4(0.f, 0.f, 0.f, 0.f);
    int c = (m > 0) ? bucket[0] : 0;
    for (int j = 0; j < m; j++) {
        int cn = (j + 1 < m) ? bucket[j + 1] : 0;
        uint2 raw = *(const uint2*)(g_Z + (size_t)c * DD + lane * 4);
        float2 p0 = __half22float2(*(__half2*)&raw.x);
        float2 p1 = __half22float2(*(__half2*)&raw.y);
        acc.x += p0.x; acc.y += p0.y; acc.z += p1.x; acc.w += p1.y;
        c = cn;
    }
    float inv = 1.0f / ((float)cnt + 1e-8f);
    float4 y  = *(const float4*)(g_Y + (size_t)node * DD + lane * 4);
    float4 bb = *(const float4*)(b + lane * 4);
    float4 o;
    o.x = fmaxf(y.x + bb.x + acc.x * inv, 0.f);
    o.y = fmaxf(y.y + bb.y + acc.y * inv, 0.f);
    o.z = fmaxf(y.z + bb.z + acc.z * inv, 0.f);
    o.w = fmaxf(y.w + bb.w + acc.w * inv, 0.f);
    *(float4*)(out + (size_t)node * DOUT + lane * 4) = o;
}

// ---------------- launch ------------------------------------------------------
extern "C" void kernel_launch(void* const* d_in, const int* in_sizes, int n_in,
                              void* d_out, int out_size) {
    const float* x   = (const float*)d_in[0];
    const void*  ei  = d_in[1];
    const float* W   = (const float*)d_in[2];
    const float* b   = (const float*)d_in[3];
    float*       out = (float*)d_out;

    cudaFuncSetAttribute(gemm_kernel,
                         cudaFuncAttributeMaxDynamicSharedMemorySize, SMEM_TOTAL);

    cudaStream_t s1;
    cudaEvent_t  e_fork, e_join;
    cudaStreamCreateWithFlags(&s1, cudaStreamNonBlocking);
    cudaEventCreateWithFlags(&e_fork, cudaEventDisableTiming);
    cudaEventCreateWithFlags(&e_join, cudaEventDisableTiming);

    cudaEventRecord(e_fork, 0);
    cudaStreamWaitEvent(s1, e_fork, 0);

    // adjacency branch (side stream)
    zero_kernel<<<(NN + 255) / 256, 256, 0, s1>>>();
    decode_bucket_kernel<<<(EE + 255) / 256, 256, 0, s1>>>(ei);
    cudaEventRecord(e_join, s1);

    // main stream: split then GEMM (overlaps bucket build)
    split_kernel<<<(NX4 + NW4 + 255) / 256, 256>>>(x, W);
    dim3 ggrid((NN + GM - 1) / GM, 2);
    gemm_kernel<<<ggrid, 256, SMEM_TOTAL>>>();

    cudaStreamWaitEvent(0, e_join, 0);
    final_kernel<<<(NN * 32 + 255) / 256, 256>>>(b, out);
}

// round 12
// speedup vs baseline: 1.0527x; 1.0063x over previous
#include <cuda_runtime.h>
#include <cuda_bf16.h>
#include <cuda_fp16.h>
#include <cstdint>

#define NN 50000
#define EE 640000
#define DD 128          // feature dim (GEMM K)
#define KK 256          // W row length (2*DD)
#define DOUT 128
#define CAP 80          // max neighbors per node (Poisson(12.8): P(>=80) ~ 1e-45)

// ---------------- scratch (static device globals; no allocation) -------------
__device__ float  g_Y[(size_t)NN * DD];     // x @ W1^T   fp32 (25.6 MB)
__device__ __half g_Z[(size_t)NN * DD];     // x @ W2^T   fp16 (12.8 MB)
__device__ int    g_bucket[(size_t)NN * CAP];  // adjacency buckets (16 MB)
__device__ int    g_cnt[NN];
// pre-split bf16 operands
__device__ __nv_bfloat16 g_xhi[(size_t)NN * DD];
__device__ __nv_bfloat16 g_xlo[(size_t)NN * DD];
__device__ __nv_bfloat16 g_whi[DOUT * KK];
__device__ __nv_bfloat16 g_wlo[DOUT * KK];

// ---------------- 0) zero counters -------------------------------------------
__global__ void zero_kernel() {
    int i = blockIdx.x * blockDim.x + threadIdx.x;
    if (i < NN) g_cnt[i] = 0;
}

// ---------------- 1) decode edge index + bucket insert (fused) ----------------
__global__ void decode_bucket_kernel(const void* __restrict__ ei) {
    const int* ei32 = (const int*)ei;
    int t = threadIdx.x;
    int accw = ei32[2 * t + 1] | ei32[2 * (t + 256) + 1];
    int is32 = __syncthreads_or(accw);      // nonzero -> int32 indices

    int e = blockIdx.x * blockDim.x + t;
    if (e >= EE) return;
    int r, c;
    if (!is32) {
        const long long* p = (const long long*)ei;
        r = (int)p[e];
        c = (int)p[(size_t)EE + e];
    } else {
        r = ei32[e];
        c = ei32[EE + e];
    }
    r = min(max(r, 0), NN - 1);
    c = min(max(c, 0), NN - 1);
    int slot = atomicAdd(&g_cnt[r], 1);
    if (slot < CAP)
        g_bucket[(size_t)r * CAP + slot] = c;
}

// ---------------- 2) one-pass bf16 hi/lo split of x and W ---------------------
#define NX4 ((NN * DD) / 4)
#define NW4 ((DOUT * KK) / 4)
__global__ void split_kernel(const float* __restrict__ x, const float* __restrict__ W) {
    int i = blockIdx.x * blockDim.x + threadIdx.x;
    if (i < NX4) {
        float4 v = ((const float4*)x)[i];
        __nv_bfloat16 h0 = __float2bfloat16(v.x), h1 = __float2bfloat16(v.y);
        __nv_bfloat16 h2 = __float2bfloat16(v.z), h3 = __float2bfloat16(v.w);
        __nv_bfloat162* hp = (__nv_bfloat162*)(g_xhi + (size_t)i * 4);
        hp[0] = __nv_bfloat162(h0, h1);
        hp[1] = __nv_bfloat162(h2, h3);
        __nv_bfloat162* lp = (__nv_bfloat162*)(g_xlo + (size_t)i * 4);
        lp[0] = __nv_bfloat162(__float2bfloat16(v.x - __bfloat162float(h0)),
                               __float2bfloat16(v.y - __bfloat162float(h1)));
        lp[1] = __nv_bfloat162(__float2bfloat16(v.z - __bfloat162float(h2)),
                               __float2bfloat16(v.w - __bfloat162float(h3)));
    } else if (i < NX4 + NW4) {
        int j = i - NX4;
        float4 v = ((const float4*)W)[j];
        __nv_bfloat16 h0 = __float2bfloat16(v.x), h1 = __float2bfloat16(v.y);
        __nv_bfloat16 h2 = __float2bfloat16(v.z), h3 = __float2bfloat16(v.w);
        __nv_bfloat162* hp = (__nv_bfloat162*)(g_whi + (size_t)j * 4);
        hp[0] = __nv_bfloat162(h0, h1);
        hp[1] = __nv_bfloat162(h2, h3);
        __nv_bfloat162* lp = (__nv_bfloat162*)(g_wlo + (size_t)j * 4);
        lp[0] = __nv_bfloat162(__float2bfloat16(v.x - __bfloat162float(h0)),
                               __float2bfloat16(v.y - __bfloat162float(h1)));
        lp[1] = __nv_bfloat162(__float2bfloat16(v.z - __bfloat162float(h2)),
                               __float2bfloat16(v.w - __bfloat162float(h3)));
    }
}

// ---------------- 3) GEMM via mma.sync + ldmatrix + cp.async double buffer ---
// [Y|Z] = x @ [W1;W2]^T, 3-term bf16 split.
// CTA tile 128(M) x 64(N); grid = (391, 4): blockIdx.y = {half, ngroup}.
// 3 CTAs/SM (regs<=85 via launch_bounds, smem 60KB) -> 24 warps/SM.
#define GM 128
#define GN 64
#define GK 32
#define ROWP 40                   // smem row stride in halves (80B, LDSM conflict-free)
#define A_TILE_B (GM * ROWP * 2)  // 10240 B per 128x32 bf16 tile
#define B_TILE_B (GN * ROWP * 2)  // 5120 B per 64x32 bf16 tile
#define STAGE_B (2 * A_TILE_B + 2 * B_TILE_B)   // 30720 B
#define SMEM_TOTAL (2 * STAGE_B)                 // 61440 B

__device__ __forceinline__ uint32_t smem_u32(const void* p) {
    uint32_t a;
    asm("{ .reg .u64 t; cvta.to.shared.u64 t, %1; cvt.u32.u64 %0, t; }"
        : "=r"(a) : "l"(p));
    return a;
}

#define LDSM4(r, addr) \
    asm volatile("ldmatrix.sync.aligned.m8n8.x4.shared.b16 {%0,%1,%2,%3}, [%4];" \
                 : "=r"((r)[0]), "=r"((r)[1]), "=r"((r)[2]), "=r"((r)[3])       \
                 : "r"(addr))

__device__ __forceinline__ void mma_bf16(float c[4], const uint32_t a[4],
                                         uint32_t b0, uint32_t b1) {
    asm volatile(
        "mma.sync.aligned.m16n8k16.row.col.f32.bf16.bf16.f32 "
        "{%0,%1,%2,%3}, {%4,%5,%6,%7}, {%8,%9}, {%0,%1,%2,%3};"
        : "+f"(c[0]), "+f"(c[1]), "+f"(c[2]), "+f"(c[3])
        : "r"(a[0]), "r"(a[1]), "r"(a[2]), "r"(a[3]), "r"(b0), "r"(b1));
}

__device__ __forceinline__ uint32_t offA(int s, int hilo) {
    return (uint32_t)(s * STAGE_B + hilo * A_TILE_B);
}
__device__ __forceinline__ uint32_t offB(int s, int hilo) {
    return (uint32_t)(s * STAGE_B + 2 * A_TILE_B + hilo * B_TILE_B);
}

// 1536 16B-chunks per stage: A 1024 (hi 512 + lo 512), B 512 (hi 256 + lo 256)
// wbias = halfsel*DD + brow0*KK  (column offset + feature-row offset combined)
__device__ __forceinline__ void load_stage(uint32_t sbase, int s, int k0,
                                           int block_m, int wbias, int t) {
#pragma unroll
    for (int j = 0; j < 6; j++) {
        int i = t + j * 256;
        const __nv_bfloat16* src;
        uint32_t dst;
        int srcsize = 16;
        if (i < 1024) {                       // A tiles
            int hilo = i >> 9;
            int idx = i & 511;
            int row = idx >> 2;
            int kq = (idx & 3) * 8;
            int grow = block_m + row;
            if (grow >= NN) { grow = NN - 1; srcsize = 0; }
            src = (hilo ? g_xlo : g_xhi) + (size_t)grow * DD + k0 + kq;
            dst = sbase + offA(s, hilo) + (uint32_t)((row * ROWP + kq) * 2);
        } else {                              // B tiles
            int bi = i - 1024;
            int hilo = bi >> 8;
            int idx = bi & 255;
            int row = idx >> 2;
            int kq = (idx & 3) * 8;
            src = (hilo ? g_wlo : g_whi) + (size_t)row * KK + wbias + k0 + kq;
            dst = sbase + offB(s, hilo) + (uint32_t)((row * ROWP + kq) * 2);
        }
        asm volatile("cp.async.cg.shared.global [%0], [%1], 16, %2;"
                     :: "r"(dst), "l"(src), "r"(srcsize));
    }
}

__global__ __launch_bounds__(256, 3)
void gemm_kernel() {
    extern __shared__ char smem[];
    uint32_t sbase = smem_u32(smem);

    int t = threadIdx.x;
    int wid = t >> 5, lane = t & 31;
    int block_m = blockIdx.x * GM;
    int halfsel = blockIdx.y >> 1;           // 0 -> Y (W1), 1 -> Z (W2)
    int ng = blockIdx.y & 1;                 // which 64-feature group
    int brow0 = ng * GN;
    int wbias = halfsel * DD + brow0 * KK;   // combined W offset
    int wm = (wid & 3) * 32;
    int wn = (wid >> 2) * 32;
    int g = lane >> 2, tig = lane & 3;
    int frow = lane & 15;
    int fcol = (lane >> 4) * 8;

    float acc[2][4][4];
#pragma unroll
    for (int mi = 0; mi < 2; mi++)
#pragma unroll
        for (int ni = 0; ni < 4; ni++)
#pragma unroll
            for (int q = 0; q < 4; q++) acc[mi][ni][q] = 0.f;

    load_stage(sbase, 0, 0, block_m, wbias, t);
    asm volatile("cp.async.commit_group;");

#pragma unroll
    for (int kt = 0; kt < 4; kt++) {
        int s = kt & 1;
        if (kt < 3) {
            load_stage(sbase, s ^ 1, (kt + 1) * GK, block_m, wbias, t);
            asm volatile("cp.async.commit_group;");
            asm volatile("cp.async.wait_group 1;");
        } else {
            asm volatile("cp.async.wait_group 0;");
        }
        __syncthreads();

        uint32_t aHi = sbase + offA(s, 0);
        uint32_t aLo = sbase + offA(s, 1);
        uint32_t bHi = sbase + offB(s, 0);
        uint32_t bLo = sbase + offB(s, 1);

#pragma unroll
        for (int kk16 = 0; kk16 < 2; kk16++) {
            int kk = kk16 * 16;
            uint32_t ah[2][4], al[2][4];
#pragma unroll
            for (int mi = 0; mi < 2; mi++) {
                uint32_t aoff = (uint32_t)(((wm + mi * 16 + frow) * ROWP
                                            + kk + fcol) * 2);
                LDSM4(ah[mi], aHi + aoff);
                LDSM4(al[mi], aLo + aoff);
            }
#pragma unroll
            for (int nj = 0; nj < 2; nj++) {
                uint32_t bh[4], bl[4];
                uint32_t boff = (uint32_t)(((wn + nj * 16 + frow) * ROWP
                                            + kk + fcol) * 2);
                LDSM4(bh, bHi + boff);
                LDSM4(bl, bLo + boff);
#pragma unroll
                for (int p = 0; p < 2; p++) {
                    int ni = nj * 2 + p;
#pragma unroll
                    for (int mi = 0; mi < 2; mi++) {
                        mma_bf16(acc[mi][ni], ah[mi], bh[p], bh[2 + p]);
                        mma_bf16(acc[mi][ni], ah[mi], bl[p], bl[2 + p]);
                        mma_bf16(acc[mi][ni], al[mi], bh[p], bh[2 + p]);
                    }
                }
            }
        }
        __syncthreads();
    }

    if (halfsel) {
#pragma unroll
        for (int mi = 0; mi < 2; mi++) {
#pragma unroll
            for (int ni = 0; ni < 4; ni++) {
                int r0 = block_m + wm + mi * 16 + g;
                int r1 = r0 + 8;
                int n = brow0 + wn + ni * 8 + 2 * tig;
                if (r0 < NN)
                    *(__half2*)(g_Z + (size_t)r0 * DD + n) =
                        __floats2half2_rn(acc[mi][ni][0], acc[mi][ni][1]);
                if (r1 < NN)
                    *(__half2*)(g_Z + (size_t)r1 * DD + n) =
                        __floats2half2_rn(acc[mi][ni][2], acc[mi][ni][3]);
            }
        }
    } else {
#pragma unroll
        for (int mi = 0; mi < 2; mi++) {
#pragma unroll
            for (int ni = 0; ni < 4; ni++) {
                int r0 = block_m + wm + mi * 16 + g;
                int r1 = r0 + 8;
                int n = brow0 + wn + ni * 8 + 2 * tig;
                if (r0 < NN)
                    *(float2*)(g_Y + (size_t)r0 * DD + n) =
                        make_float2(acc[mi][ni][0], acc[mi][ni][1]);
                if (r1 < NN)
                    *(float2*)(g_Y + (size_t)r1 * DD + n) =
                        make_float2(acc[mi][ni][2], acc[mi][ni][3]);
            }
        }
    }
}

// ---------------- 4) fused gather + epilogue ----------------------------------
__global__ void final_kernel(const float* __restrict__ b, float* __restrict__ out) {
    int gtid = blockIdx.x * blockDim.x + threadIdx.x;
    int node = gtid >> 5;
    int lane = gtid & 31;
    if (node >= NN) return;
    int cnt = g_cnt[node];
    int m = min(cnt, CAP);
    const int* bucket = g_bucket + (size_t)node * CAP;
    float4 acc = make_float4(0.f, 0.f, 0.f, 0.f);
    int c = (m > 0) ? bucket[0] : 0;
    for (int j = 0; j < m; j++) {
        int cn = (j + 1 < m) ? bucket[j + 1] : 0;
        uint2 raw = *(const uint2*)(g_Z + (size_t)c * DD + lane * 4);
        float2 p0 = __half22float2(*(__half2*)&raw.x);
        float2 p1 = __half22float2(*(__half2*)&raw.y);
        acc.x += p0.x; acc.y += p0.y; acc.z += p1.x; acc.w += p1.y;
        c = cn;
    }
    float inv = 1.0f / ((float)cnt + 1e-8f);
    float4 y  = *(const float4*)(g_Y + (size_t)node * DD + lane * 4);
    float4 bb = *(const float4*)(b + lane * 4);
    float4 o;
    o.x = fmaxf(y.x + bb.x + acc.x * inv, 0.f);
    o.y = fmaxf(y.y + bb.y + acc.y * inv, 0.f);
    o.z = fmaxf(y.z + bb.z + acc.z * inv, 0.f);
    o.w = fmaxf(y.w + bb.w + acc.w * inv, 0.f);
    *(float4*)(out + (size_t)node * DOUT + lane * 4) = o;
}

// ---------------- launch ------------------------------------------------------
extern "C" void kernel_launch(void* const* d_in, const int* in_sizes, int n_in,
                              void* d_out, int out_size) {
    const float* x   = (const float*)d_in[0];
    const void*  ei  = d_in[1];
    const float* W   = (const float*)d_in[2];
    const float* b   = (const float*)d_in[3];
    float*       out = (float*)d_out;

    cudaFuncSetAttribute(gemm_kernel,
                         cudaFuncAttributeMaxDynamicSharedMemorySize, SMEM_TOTAL);

    cudaStream_t s1;
    cudaEvent_t  e_fork, e_join;
    cudaStreamCreateWithFlags(&s1, cudaStreamNonBlocking);
    cudaEventCreateWithFlags(&e_fork, cudaEventDisableTiming);
    cudaEventCreateWithFlags(&e_join, cudaEventDisableTiming);

    cudaEventRecord(e_fork, 0);
    cudaStreamWaitEvent(s1, e_fork, 0);

    // adjacency branch (side stream)
    zero_kernel<<<(NN + 255) / 256, 256, 0, s1>>>();
    decode_bucket_kernel<<<(EE + 255) / 256, 256, 0, s1>>>(ei);
    cudaEventRecord(e_join, s1);

    // main stream: split then GEMM (overlaps bucket build)
    split_kernel<<<(NX4 + NW4 + 255) / 256, 256>>>(x, W);
    dim3 ggrid((NN + GM - 1) / GM, 4);
    gemm_kernel<<<ggrid, 256, SMEM_TOTAL>>>();

    cudaStreamWaitEvent(0, e_join, 0);
    final_kernel<<<(NN * 32 + 255) / 256, 256>>>(b, out);
}

// round 13
// speedup vs baseline: 1.3815x; 1.3124x over previous
#include <cuda_runtime.h>
#include <cuda_bf16.h>
#include <cuda_fp16.h>
#include <cstdint>

#define NN 50000
#define EE 640000
#define DD 128          // feature dim (GEMM K)
#define KK 256          // W row length (2*DD)
#define DOUT 128
#define CAP 80          // max neighbors per node (Poisson(12.8): P(>=80) ~ 1e-45)

// ---------------- scratch (static device globals; no allocation) -------------
__device__ float  g_Y[(size_t)NN * DD];     // x @ W1^T   fp32 (25.6 MB)
__device__ __half g_Z[(size_t)NN * DD];     // x @ W2^T   fp16 (12.8 MB)
__device__ int    g_bucket[(size_t)NN * CAP];  // adjacency buckets (16 MB)
__device__ int    g_cnt[NN];
// fp16 operands
__device__ __half g_xh[(size_t)NN * DD];    // x in fp16 (12.8 MB)
__device__ __half g_wh[DOUT * KK];          // W in fp16

// ---------------- 0) zero counters -------------------------------------------
__global__ void zero_kernel() {
    int i = blockIdx.x * blockDim.x + threadIdx.x;
    if (i < NN) g_cnt[i] = 0;
}

// ---------------- 1) decode edge index + bucket insert (fused) ----------------
__global__ void decode_bucket_kernel(const void* __restrict__ ei) {
    const int* ei32 = (const int*)ei;
    int t = threadIdx.x;
    int accw = ei32[2 * t + 1] | ei32[2 * (t + 256) + 1];
    int is32 = __syncthreads_or(accw);      // nonzero -> int32 indices

    int e = blockIdx.x * blockDim.x + t;
    if (e >= EE) return;
    int r, c;
    if (!is32) {
        const long long* p = (const long long*)ei;
        r = (int)p[e];
        c = (int)p[(size_t)EE + e];
    } else {
        r = ei32[e];
        c = ei32[EE + e];
    }
    r = min(max(r, 0), NN - 1);
    c = min(max(c, 0), NN - 1);
    int slot = atomicAdd(&g_cnt[r], 1);
    if (slot < CAP)
        g_bucket[(size_t)r * CAP + slot] = c;
}

// ---------------- 2) one-pass fp16 convert of x and W -------------------------
#define NX4 ((NN * DD) / 4)
#define NW4 ((DOUT * KK) / 4)
__global__ void split_kernel(const float* __restrict__ x, const float* __restrict__ W) {
    int i = blockIdx.x * blockDim.x + threadIdx.x;
    if (i < NX4) {
        float4 v = ((const float4*)x)[i];
        __half2 h01 = __floats2half2_rn(v.x, v.y);
        __half2 h23 = __floats2half2_rn(v.z, v.w);
        uint2 pk;
        pk.x = *(uint32_t*)&h01;
        pk.y = *(uint32_t*)&h23;
        *(uint2*)(g_xh + (size_t)i * 4) = pk;
    } else if (i < NX4 + NW4) {
        int j = i - NX4;
        float4 v = ((const float4*)W)[j];
        __half2 h01 = __floats2half2_rn(v.x, v.y);
        __half2 h23 = __floats2half2_rn(v.z, v.w);
        uint2 pk;
        pk.x = *(uint32_t*)&h01;
        pk.y = *(uint32_t*)&h23;
        *(uint2*)(g_wh + (size_t)j * 4) = pk;
    }
}

// ---------------- 3) GEMM via fp16 mma.sync + ldmatrix + cp.async -------------
// [Y|Z] = x @ [W1;W2]^T, single-term fp16 (fp32 accumulate).
// CTA tile 128(M) x 64(N); grid = (391, 4): blockIdx.y = {half, ngroup}.
#define GM 128
#define GN 64
#define GK 32
#define ROWP 40                   // smem row stride in halves (80B, LDSM conflict-free)
#define A_TILE_B (GM * ROWP * 2)  // 10240 B per 128x32 fp16 tile
#define B_TILE_B (GN * ROWP * 2)  // 5120 B per 64x32 fp16 tile
#define STAGE_B (A_TILE_B + B_TILE_B)            // 15360 B
#define SMEM_TOTAL (2 * STAGE_B)                 // 30720 B

__device__ __forceinline__ uint32_t smem_u32(const void* p) {
    uint32_t a;
    asm("{ .reg .u64 t; cvta.to.shared.u64 t, %1; cvt.u32.u64 %0, t; }"
        : "=r"(a) : "l"(p));
    return a;
}

#define LDSM4(r, addr) \
    asm volatile("ldmatrix.sync.aligned.m8n8.x4.shared.b16 {%0,%1,%2,%3}, [%4];" \
                 : "=r"((r)[0]), "=r"((r)[1]), "=r"((r)[2]), "=r"((r)[3])       \
                 : "r"(addr))

__device__ __forceinline__ void mma_fp16(float c[4], const uint32_t a[4],
                                         uint32_t b0, uint32_t b1) {
    asm volatile(
        "mma.sync.aligned.m16n8k16.row.col.f32.f16.f16.f32 "
        "{%0,%1,%2,%3}, {%4,%5,%6,%7}, {%8,%9}, {%0,%1,%2,%3};"
        : "+f"(c[0]), "+f"(c[1]), "+f"(c[2]), "+f"(c[3])
        : "r"(a[0]), "r"(a[1]), "r"(a[2]), "r"(a[3]), "r"(b0), "r"(b1));
}

__device__ __forceinline__ uint32_t offA(int s) { return (uint32_t)(s * STAGE_B); }
__device__ __forceinline__ uint32_t offB(int s) {
    return (uint32_t)(s * STAGE_B + A_TILE_B);
}

// 768 16B-chunks per stage: A 512, B 256; 3 per thread
// wbias = halfsel*DD + brow0*KK  (column offset + feature-row offset combined)
__device__ __forceinline__ void load_stage(uint32_t sbase, int s, int k0,
                                           int block_m, int wbias, int t) {
#pragma unroll
    for (int j = 0; j < 3; j++) {
        int i = t + j * 256;
        const __half* src;
        uint32_t dst;
        int srcsize = 16;
        if (i < 512) {                        // A tile
            int row = i >> 2;
            int kq = (i & 3) * 8;
            int grow = block_m + row;
            if (grow >= NN) { grow = NN - 1; srcsize = 0; }
            src = g_xh + (size_t)grow * DD + k0 + kq;
            dst = sbase + offA(s) + (uint32_t)((row * ROWP + kq) * 2);
        } else {                              // B tile
            int bi = i - 512;
            int row = bi >> 2;
            int kq = (bi & 3) * 8;
            src = g_wh + (size_t)row * KK + wbias + k0 + kq;
            dst = sbase + offB(s) + (uint32_t)((row * ROWP + kq) * 2);
        }
        asm volatile("cp.async.cg.shared.global [%0], [%1], 16, %2;"
                     :: "r"(dst), "l"(src), "r"(srcsize));
    }
}

__global__ __launch_bounds__(256, 3)
void gemm_kernel() {
    extern __shared__ char smem[];
    uint32_t sbase = smem_u32(smem);

    int t = threadIdx.x;
    int wid = t >> 5, lane = t & 31;
    int block_m = blockIdx.x * GM;
    int halfsel = blockIdx.y >> 1;           // 0 -> Y (W1), 1 -> Z (W2)
    int ng = blockIdx.y & 1;                 // which 64-feature group
    int brow0 = ng * GN;
    int wbias = halfsel * DD + brow0 * KK;   // combined W offset
    int wm = (wid & 3) * 32;
    int wn = (wid >> 2) * 32;
    int g = lane >> 2, tig = lane & 3;
    int frow = lane & 15;
    int fcol = (lane >> 4) * 8;

    float acc[2][4][4];
#pragma unroll
    for (int mi = 0; mi < 2; mi++)
#pragma unroll
        for (int ni = 0; ni < 4; ni++)
#pragma unroll
            for (int q = 0; q < 4; q++) acc[mi][ni][q] = 0.f;

    load_stage(sbase, 0, 0, block_m, wbias, t);
    asm volatile("cp.async.commit_group;");

#pragma unroll
    for (int kt = 0; kt < 4; kt++) {
        int s = kt & 1;
        if (kt < 3) {
            load_stage(sbase, s ^ 1, (kt + 1) * GK, block_m, wbias, t);
            asm volatile("cp.async.commit_group;");
            asm volatile("cp.async.wait_group 1;");
        } else {
            asm volatile("cp.async.wait_group 0;");
        }
        __syncthreads();

        uint32_t aT = sbase + offA(s);
        uint32_t bT = sbase + offB(s);

#pragma unroll
        for (int kk16 = 0; kk16 < 2; kk16++) {
            int kk = kk16 * 16;
            uint32_t ah[2][4];
#pragma unroll
            for (int mi = 0; mi < 2; mi++) {
                uint32_t aoff = (uint32_t)(((wm + mi * 16 + frow) * ROWP
                                            + kk + fcol) * 2);
                LDSM4(ah[mi], aT + aoff);
            }
#pragma unroll
            for (int nj = 0; nj < 2; nj++) {
                uint32_t bh[4];
                uint32_t boff = (uint32_t)(((wn + nj * 16 + frow) * ROWP
                                            + kk + fcol) * 2);
                LDSM4(bh, bT + boff);
#pragma unroll
                for (int p = 0; p < 2; p++) {
                    int ni = nj * 2 + p;
#pragma unroll
                    for (int mi = 0; mi < 2; mi++)
                        mma_fp16(acc[mi][ni], ah[mi], bh[p], bh[2 + p]);
                }
            }
        }
        __syncthreads();
    }

    if (halfsel) {
#pragma unroll
        for (int mi = 0; mi < 2; mi++) {
#pragma unroll
            for (int ni = 0; ni < 4; ni++) {
                int r0 = block_m + wm + mi * 16 + g;
                int r1 = r0 + 8;
                int n = brow0 + wn + ni * 8 + 2 * tig;
                if (r0 < NN)
                    *(__half2*)(g_Z + (size_t)r0 * DD + n) =
                        __floats2half2_rn(acc[mi][ni][0], acc[mi][ni][1]);
                if (r1 < NN)
                    *(__half2*)(g_Z + (size_t)r1 * DD + n) =
                        __floats2half2_rn(acc[mi][ni][2], acc[mi][ni][3]);
            }
        }
    } else {
#pragma unroll
        for (int mi = 0; mi < 2; mi++) {
#pragma unroll
            for (int ni = 0; ni < 4; ni++) {
                int r0 = block_m + wm + mi * 16 + g;
                int r1 = r0 + 8;
                int n = brow0 + wn + ni * 8 + 2 * tig;
                if (r0 < NN)
                    *(float2*)(g_Y + (size_t)r0 * DD + n) =
                        make_float2(acc[mi][ni][0], acc[mi][ni][1]);
                if (r1 < NN)
                    *(float2*)(g_Y + (size_t)r1 * DD + n) =
                        make_float2(acc[mi][ni][2], acc[mi][ni][3]);
            }
        }
    }
}

// ---------------- 4) fused gather + epilogue ----------------------------------
__global__ void final_kernel(const float* __restrict__ b, float* __restrict__ out) {
    int gtid = blockIdx.x * blockDim.x + threadIdx.x;
    int node = gtid >> 5;
    int lane = gtid & 31;
    if (node >= NN) return;
    int cnt = g_cnt[node];
    int m = min(cnt, CAP);
    const int* bucket = g_bucket + (size_t)node * CAP;
    float4 acc = make_float4(0.f, 0.f, 0.f, 0.f);
    int c = (m > 0) ? bucket[0] : 0;
    for (int j = 0; j < m; j++) {
        int cn = (j + 1 < m) ? bucket[j + 1] : 0;
        uint2 raw = *(const uint2*)(g_Z + (size_t)c * DD + lane * 4);
        float2 p0 = __half22float2(*(__half2*)&raw.x);
        float2 p1 = __half22float2(*(__half2*)&raw.y);
        acc.x += p0.x; acc.y += p0.y; acc.z += p1.x; acc.w += p1.y;
        c = cn;
    }
    float inv = 1.0f / ((float)cnt + 1e-8f);
    float4 y  = *(const float4*)(g_Y + (size_t)node * DD + lane * 4);
    float4 bb = *(const float4*)(b + lane * 4);
    float4 o;
    o.x = fmaxf(y.x + bb.x + acc.x * inv, 0.f);
    o.y = fmaxf(y.y + bb.y + acc.y * inv, 0.f);
    o.z = fmaxf(y.z + bb.z + acc.z * inv, 0.f);
    o.w = fmaxf(y.w + bb.w + acc.w * inv, 0.f);
    *(float4*)(out + (size_t)node * DOUT + lane * 4) = o;
}

// ---------------- launch ------------------------------------------------------
extern "C" void kernel_launch(void* const* d_in, const int* in_sizes, int n_in,
                              void* d_out, int out_size) {
    const float* x   = (const float*)d_in[0];
    const void*  ei  = d_in[1];
    const float* W   = (const float*)d_in[2];
    const float* b   = (const float*)d_in[3];
    float*       out = (float*)d_out;

    cudaFuncSetAttribute(gemm_kernel,
                         cudaFuncAttributeMaxDynamicSharedMemorySize, SMEM_TOTAL);

    cudaStream_t s1;
    cudaEvent_t  e_fork, e_join;
    cudaStreamCreateWithFlags(&s1, cudaStreamNonBlocking);
    cudaEventCreateWithFlags(&e_fork, cudaEventDisableTiming);
    cudaEventCreateWithFlags(&e_join, cudaEventDisableTiming);

    cudaEventRecord(e_fork, 0);
    cudaStreamWaitEvent(s1, e_fork, 0);

    // adjacency branch (side stream)
    zero_kernel<<<(NN + 255) / 256, 256, 0, s1>>>();
    decode_bucket_kernel<<<(EE + 255) / 256, 256, 0, s1>>>(ei);
    cudaEventRecord(e_join, s1);

    // main stream: fp16 convert then GEMM (overlaps bucket build)
    split_kernel<<<(NX4 + NW4 + 255) / 256, 256>>>(x, W);
    dim3 ggrid((NN + GM - 1) / GM, 4);
    gemm_kernel<<<ggrid, 256, SMEM_TOTAL>>>();

    cudaStreamWaitEvent(0, e_join, 0);
    final_kernel<<<(NN * 32 + 255) / 256, 256>>>(b, out);
}